// round 9
// baseline (speedup 1.0000x reference)
#include <cuda_runtime.h>
#include <cuda_bf16.h>
#include <cstdint>

// ---------------------------------------------------------------------------
// Problem constants
// ---------------------------------------------------------------------------
#define N_ROWS 4096
#define DIM    2048
#define HALF   2048
#define TILE_M 128
#define KC     128                // int8 elems per K chunk (128 B per row)
#define NKC    (DIM / KC)         // 16 chunks
#define NSLOT  128                // row-partial slots per row (32-col granularity)
#define LT     16                 // left-half 128-tiles per side
#define NTILES_TRI (LT * (LT + 1) / 2)   // 136 upper-tri incl diag
#define NFULL_R 160                      // right-half full tiles (tileM 0..9)
#define NFULL  (NTILES_TRI + NFULL_R)    // 296 full jobs
#define NQUART 384                       // 96 split tiles x 4 quarters
#define NBLOCKS (NFULL + NQUART)         // 680
#define MARGIN_F 0.3f
#define SLAB_BYTES ((size_t)N_ROWS * 128)   // bytes per K-chunk slab in g_Aq

// SMEM layout (dynamic)
#define STAGE_BYTES 32768         // A tile 16KB + B tile up to 16KB
#define STAGES 3
#define OFF_MBAR 98304            // 3 x 8B mbarriers
#define OFF_SQC  98432            // 128 floats
#define OFF_TGC  98944
#define OFF_SQR  99456
#define OFF_TGR  99968
#define OFF_SCR  100480
#define OFF_SCC  100992
#define OFF_RAP  101504           // 128*4 floats (row partials)
#define OFF_RAN  103552
#define OFF_CAP  105600           // 128*2 floats (col partials)
#define OFF_CAN  106624
#define SMEM_TOTAL 107648

// Scratch (__device__ globals; allocation-free rule)
// g_Aq layout: [chunk][row][128B], SW128 swizzle pre-applied, so any 32/128-row
// slab is contiguous and bulk-copies directly into the ldmatrix-ready image.
__device__ __align__(128) int8_t g_Aq[(size_t)N_ROWS * DIM];   // 8 MB
__device__ float g_sq[N_ROWS];
__device__ float g_scale[N_ROWS];
__device__ float g_ap[HALF * NSLOT];    // 1 MB
__device__ float g_an[HALF * NSLOT];

// ---------------------------------------------------------------------------
// PTX helpers
// ---------------------------------------------------------------------------
__device__ __forceinline__ uint32_t smem_u32(const void* p) {
    uint32_t a;
    asm("{ .reg .u64 t; cvta.to.shared.u64 t, %1; cvt.u32.u64 %0, t; }" : "=r"(a) : "l"(p));
    return a;
}
__device__ __forceinline__ void mbar_init(uint32_t a, uint32_t cnt) {
    asm volatile("mbarrier.init.shared.b64 [%0], %1;" :: "r"(a), "r"(cnt) : "memory");
}
__device__ __forceinline__ void mbar_expect_tx(uint32_t a, uint32_t bytes) {
    asm volatile("mbarrier.arrive.expect_tx.shared.b64 _, [%0], %1;"
                 :: "r"(a), "r"(bytes) : "memory");
}
__device__ __forceinline__ void mbar_wait(uint32_t a, uint32_t parity) {
    asm volatile(
        "{\n\t.reg .pred P;\n"
        "W_%=:\n\t"
        "mbarrier.try_wait.parity.shared.b64 P, [%0], %1, 0x989680;\n\t"
        "@P bra.uni D_%=;\n\t"
        "bra.uni W_%=;\n"
        "D_%=:\n\t}"
        :: "r"(a), "r"(parity) : "memory");
}
__device__ __forceinline__ void bulk_g2s(uint32_t sdst, const void* gsrc,
                                         uint32_t bytes, uint32_t mbar) {
    asm volatile(
        "cp.async.bulk.shared::cta.global.mbarrier::complete_tx::bytes [%0], [%1], %2, [%3];"
        :: "r"(sdst), "l"(gsrc), "r"(bytes), "r"(mbar) : "memory");
}
__device__ __forceinline__ void ldmatrix_x4(uint32_t* r, uint32_t addr) {
    asm volatile("ldmatrix.sync.aligned.m8n8.x4.shared.b16 {%0,%1,%2,%3}, [%4];"
                 : "=r"(r[0]), "=r"(r[1]), "=r"(r[2]), "=r"(r[3]) : "r"(addr));
}
__device__ __forceinline__ void mma_s8(int* c, const uint32_t* a, uint32_t b0, uint32_t b1) {
    asm volatile(
        "mma.sync.aligned.m16n8k32.row.col.s32.s8.s8.s32 "
        "{%0,%1,%2,%3}, {%4,%5,%6,%7}, {%8,%9}, {%0,%1,%2,%3};"
        : "+r"(c[0]), "+r"(c[1]), "+r"(c[2]), "+r"(c[3])
        : "r"(a[0]), "r"(a[1]), "r"(a[2]), "r"(a[3]), "r"(b0), "r"(b1));
}
// SW128 swizzle on a 128-byte row: 16B chunk index XOR (row & 7)
__device__ __forceinline__ uint32_t sw_off(uint32_t r, uint32_t c8) {
    return r * 128u + ((c8 ^ (r & 7u)) << 4);
}

// ---------------------------------------------------------------------------
// Kernel 1: per-row absmax quantize fp32 -> int8 (pre-swizzled chunk-blocked
// layout) + row sum-of-squares (fp32). One block (128 thr, MLP 4) per row.
// ---------------------------------------------------------------------------
__global__ void quant_sq_kernel(const float* __restrict__ A) {
    const int row = blockIdx.x;
    const int tid = threadIdx.x;
    const float4* a4 = reinterpret_cast<const float4*>(A + (size_t)row * DIM);
    float4 v[4];
    #pragma unroll
    for (int i = 0; i < 4; i++) v[i] = a4[tid + i * 128];

    float s = 0.f, m = 0.f;
    #pragma unroll
    for (int i = 0; i < 4; i++) {
        s += v[i].x * v[i].x + v[i].y * v[i].y + v[i].z * v[i].z + v[i].w * v[i].w;
        m = fmaxf(m, fmaxf(fmaxf(fabsf(v[i].x), fabsf(v[i].y)),
                           fmaxf(fabsf(v[i].z), fabsf(v[i].w))));
    }
    #pragma unroll
    for (int o = 16; o > 0; o >>= 1) {
        s += __shfl_xor_sync(0xffffffffu, s, o);
        m = fmaxf(m, __shfl_xor_sync(0xffffffffu, m, o));
    }
    __shared__ float sm_s[4], sm_m[4];
    if ((tid & 31) == 0) { sm_s[tid >> 5] = s; sm_m[tid >> 5] = m; }
    __syncthreads();
    float ts = sm_s[0] + sm_s[1] + sm_s[2] + sm_s[3];
    float tm = fmaxf(fmaxf(sm_m[0], sm_m[1]), fmaxf(sm_m[2], sm_m[3]));
    if (tid == 0) {
        g_sq[row] = ts;
        g_scale[row] = fmaxf(tm, 1e-30f) / 127.0f;
    }
    const float inv = 127.0f / fmaxf(tm, 1e-30f);

    uint32_t* q32 = reinterpret_cast<uint32_t*>(g_Aq);
    auto pack = [inv](float4 vv) -> uint32_t {
        int q0 = __float2int_rn(vv.x * inv), q1 = __float2int_rn(vv.y * inv);
        int q2 = __float2int_rn(vv.z * inv), q3 = __float2int_rn(vv.w * inv);
        return (uint32_t)(uint8_t)(int8_t)q0 | ((uint32_t)(uint8_t)(int8_t)q1 << 8) |
               ((uint32_t)(uint8_t)(int8_t)q2 << 16) | ((uint32_t)(uint8_t)(int8_t)q3 << 24);
    };
    // j32 = 4-byte column index in [0, 512). chunk = j32>>5; c8 = (j32>>2)&7.
    auto qidx = [row](int j32) -> size_t {
        const int c  = j32 >> 5;
        const int c8 = (j32 >> 2) & 7;
        const int ww = j32 & 3;
        const size_t byteoff = (size_t)c * SLAB_BYTES + (size_t)row * 128 +
                               (size_t)(((uint32_t)c8 ^ ((uint32_t)row & 7u)) << 4) + ww * 4;
        return byteoff >> 2;
    };
    #pragma unroll
    for (int i = 0; i < 4; i++) q32[qidx(tid + i * 128)] = pack(v[i]);
}

// ---------------------------------------------------------------------------
// Tile worker: NJ = n8-fragments per warp (4 => 128-wide tile, 1 => 32-wide).
// ---------------------------------------------------------------------------
template<int NJ>
__device__ __forceinline__ void run_tile(char* smem, uint32_t sb, int rowBase, int colBase,
                                         int tileM, bool doTrans,
                                         const int* __restrict__ targets) {
    const int tid = threadIdx.x;
    const int lane = tid & 31;
    const int w = tid >> 5;
    const int BW = NJ * 32;                    // tile width in columns
    const uint32_t bBytes = (uint32_t)BW * 128;
    const int slotBase = colBase >> 5;

    float* s_sqc = reinterpret_cast<float*>(smem + OFF_SQC);
    int*   s_tgc = reinterpret_cast<int*>(smem + OFF_TGC);
    float* s_sqr = reinterpret_cast<float*>(smem + OFF_SQR);
    int*   s_tgr = reinterpret_cast<int*>(smem + OFF_TGR);
    float* s_scr = reinterpret_cast<float*>(smem + OFF_SCR);
    float* s_scc = reinterpret_cast<float*>(smem + OFF_SCC);
    float* s_rap = reinterpret_cast<float*>(smem + OFF_RAP);
    float* s_ran = reinterpret_cast<float*>(smem + OFF_RAN);
    float* s_cap = reinterpret_cast<float*>(smem + OFF_CAP);
    float* s_can = reinterpret_cast<float*>(smem + OFF_CAN);

    if (tid == 0) {
        #pragma unroll
        for (int s = 0; s < STAGES; ++s) mbar_init(sb + OFF_MBAR + s * 8, 1);
    }
    if (tid < BW) {
        s_sqc[tid] = g_sq[colBase + tid];
        s_tgc[tid] = targets[colBase + tid];
        s_scc[tid] = g_scale[colBase + tid];
    }
    if (tid < TILE_M) {
        s_sqr[tid] = g_sq[rowBase + tid];
        s_tgr[tid] = targets[rowBase + tid];
        s_scr[tid] = g_scale[rowBase + tid];
    }
    __syncthreads();

    auto issue_chunk = [&](int s, int chunk) {
        const uint32_t mbar = sb + OFF_MBAR + s * 8;
        const uint32_t st = sb + (uint32_t)s * STAGE_BYTES;
        mbar_expect_tx(mbar, 16384u + bBytes);
        bulk_g2s(st, g_Aq + (size_t)chunk * SLAB_BYTES + (size_t)rowBase * 128,
                 16384u, mbar);
        bulk_g2s(st + 16384u, g_Aq + (size_t)chunk * SLAB_BYTES + (size_t)colBase * 128,
                 bBytes, mbar);
    };
    if (tid == 0) {
        issue_chunk(0, 0);
        issue_chunk(1, 1);
        issue_chunk(2, 2);
    }

    int acc[4][NJ][4];
    #pragma unroll
    for (int i = 0; i < 4; i++)
        #pragma unroll
        for (int j = 0; j < NJ; j++)
            #pragma unroll
            for (int e = 0; e < 4; e++) acc[i][j][e] = 0;

    const int mBase = (w >> 2) * 64;
    const int nBase = (w & 3) * (NJ * 8);
    uint32_t ph0 = 0, ph1 = 0, ph2 = 0;

    for (int c = 0; c < NKC; ++c) {
        const int s = c % STAGES;
        uint32_t& ph = (s == 0) ? ph0 : (s == 1) ? ph1 : ph2;
        mbar_wait(sb + OFF_MBAR + s * 8, ph & 1);
        ph++;

        const uint32_t stA = sb + (uint32_t)s * STAGE_BYTES;
        const uint32_t stB = stA + 16384u;

        uint32_t bq[2][4];                      // quarter path: whole chunk's B
        if (NJ == 1) {
            #pragma unroll
            for (int p = 0; p < 2; ++p)
                ldmatrix_x4(bq[p], stB + sw_off(nBase + (lane & 7), p * 4 + (lane >> 3)));
        }

        #pragma unroll
        for (int ks = 0; ks < 4; ++ks) {        // 4 x k32(int8) per 128-chunk
            uint32_t a[4][4];
            #pragma unroll
            for (int mi = 0; mi < 4; ++mi) {
                const uint32_t r = mBase + mi * 16 + (lane & 15);
                const uint32_t c8 = ks * 2 + (lane >> 4);
                ldmatrix_x4(a[mi], stA + sw_off(r, c8));
            }
            if (NJ == 4) {
                uint32_t b[2][4];
                #pragma unroll
                for (int nb = 0; nb < 2; ++nb) {
                    const uint32_t r = nBase + nb * 16 + ((lane >> 4) << 3) + (lane & 7);
                    const uint32_t c8 = ks * 2 + ((lane >> 3) & 1);
                    ldmatrix_x4(b[nb], stB + sw_off(r, c8));
                }
                #pragma unroll
                for (int mi = 0; mi < 4; ++mi)
                    #pragma unroll
                    for (int nj = 0; nj < NJ; ++nj)
                        mma_s8(acc[mi][nj], a[mi], b[nj >> 1][(nj & 1) * 2],
                               b[nj >> 1][(nj & 1) * 2 + 1]);
            } else {
                #pragma unroll
                for (int mi = 0; mi < 4; ++mi)
                    mma_s8(acc[mi][0], a[mi], bq[ks >> 1][(ks & 1) * 2],
                           bq[ks >> 1][(ks & 1) * 2 + 1]);
            }
        }
        __syncthreads();
        if (tid == 0 && c + STAGES < NKC) issue_chunk(s, c + STAGES);
    }

    // ---- Epilogue ----
    const int qrow = lane >> 2;
    const int qcol = lane & 3;

    // Pass 0: int accumulators -> distances in place (bitcast storage).
    float* dv = reinterpret_cast<float*>(&acc[0][0][0]);
    #pragma unroll
    for (int mi = 0; mi < 4; ++mi) {
        #pragma unroll
        for (int h = 0; h < 2; ++h) {
            const int rl = mBase + mi * 16 + qrow + h * 8;
            const float sqr = s_sqr[rl];
            const float sr2 = 2.0f * s_scr[rl];
            #pragma unroll
            for (int nj = 0; nj < NJ; ++nj) {
                #pragma unroll
                for (int cc = 0; cc < 2; ++cc) {
                    const int cl = nBase + nj * 8 + qcol * 2 + cc;
                    const int e = h * 2 + cc;
                    const float dot = sr2 * s_scc[cl] * (float)acc[mi][nj][e];
                    const float d2 = sqr + s_sqc[cl] - dot;
                    dv[(mi * NJ + nj) * 4 + e] = sqrtf(fmaxf(d2, 1e-12f));
                }
            }
        }
    }

    // Pass 1: row-side masked max/min.
    #pragma unroll
    for (int mi = 0; mi < 4; ++mi) {
        #pragma unroll
        for (int h = 0; h < 2; ++h) {
            const int rl = mBase + mi * 16 + qrow + h * 8;
            const int tgr = s_tgr[rl];
            float ap = -1e30f, an = 1e30f;
            #pragma unroll
            for (int nj = 0; nj < NJ; ++nj) {
                #pragma unroll
                for (int cc = 0; cc < 2; ++cc) {
                    const int cl = nBase + nj * 8 + qcol * 2 + cc;
                    const float d = dv[(mi * NJ + nj) * 4 + h * 2 + cc];
                    if (s_tgc[cl] == tgr) ap = fmaxf(ap, d);
                    else                  an = fminf(an, d);
                }
            }
            ap = fmaxf(ap, __shfl_xor_sync(0xffffffffu, ap, 1));
            ap = fmaxf(ap, __shfl_xor_sync(0xffffffffu, ap, 2));
            an = fminf(an, __shfl_xor_sync(0xffffffffu, an, 1));
            an = fminf(an, __shfl_xor_sync(0xffffffffu, an, 2));
            if (qcol == 0) {
                s_rap[rl * 4 + (w & 3)] = ap;
                s_ran[rl * 4 + (w & 3)] = an;
            }
        }
    }

    // Pass 2 (off-diagonal tri tiles, full only): column-side masked max/min.
    if (NJ == 4 && doTrans) {
        #pragma unroll
        for (int nj = 0; nj < NJ; ++nj) {
            #pragma unroll
            for (int cc = 0; cc < 2; ++cc) {
                const int cl = nBase + nj * 8 + qcol * 2 + cc;
                const int tgc = s_tgc[cl];
                float ap = -1e30f, an = 1e30f;
                #pragma unroll
                for (int mi = 0; mi < 4; ++mi) {
                    #pragma unroll
                    for (int h = 0; h < 2; ++h) {
                        const int rl = mBase + mi * 16 + qrow + h * 8;
                        const float d = dv[(mi * NJ + nj) * 4 + h * 2 + cc];
                        if (s_tgr[rl] == tgc) ap = fmaxf(ap, d);
                        else                  an = fminf(an, d);
                    }
                }
                ap = fmaxf(ap, __shfl_xor_sync(0xffffffffu, ap, 4));
                ap = fmaxf(ap, __shfl_xor_sync(0xffffffffu, ap, 8));
                ap = fmaxf(ap, __shfl_xor_sync(0xffffffffu, ap, 16));
                an = fminf(an, __shfl_xor_sync(0xffffffffu, an, 4));
                an = fminf(an, __shfl_xor_sync(0xffffffffu, an, 8));
                an = fminf(an, __shfl_xor_sync(0xffffffffu, an, 16));
                if (qrow == 0) {
                    s_cap[cl * 2 + (w >> 2)] = ap;
                    s_can[cl * 2 + (w >> 2)] = an;
                }
            }
        }
    }
    __syncthreads();

    if (tid < TILE_M) {
        float ap = -1e30f, an = 1e30f;
        #pragma unroll
        for (int t = 0; t < 4; ++t) {
            ap = fmaxf(ap, s_rap[tid * 4 + t]);
            an = fminf(an, s_ran[tid * 4 + t]);
        }
        if (NJ == 4) {
            #pragma unroll
            for (int s = 0; s < 4; ++s) {
                g_ap[(size_t)(rowBase + tid) * NSLOT + slotBase + s] = ap;
                g_an[(size_t)(rowBase + tid) * NSLOT + slotBase + s] = an;
            }
        } else {
            g_ap[(size_t)(rowBase + tid) * NSLOT + slotBase] = ap;
            g_an[(size_t)(rowBase + tid) * NSLOT + slotBase] = an;
        }
        if (NJ == 4 && doTrans) {
            const float cap = fmaxf(s_cap[tid * 2], s_cap[tid * 2 + 1]);
            const float can = fminf(s_can[tid * 2], s_can[tid * 2 + 1]);
            #pragma unroll
            for (int s = 0; s < 4; ++s) {
                g_ap[(size_t)(colBase + tid) * NSLOT + 4 * tileM + s] = cap;
                g_an[(size_t)(colBase + tid) * NSLOT + 4 * tileM + s] = can;
            }
        }
    }
}

// ---------------------------------------------------------------------------
// Kernel 2: 296 full jobs (136 tri + 160 right) first, then 384 quarter jobs.
// ---------------------------------------------------------------------------
__global__ __launch_bounds__(256, 2)
void dist_imma_kernel(const int* __restrict__ targets) {
    extern __shared__ __align__(128) char smem[];
    const uint32_t sb = smem_u32(smem);

    int idx = blockIdx.x;
    if (idx < NTILES_TRI) {
        int a = 0, t = idx;
        #pragma unroll 1
        while (t >= LT - a) { t -= LT - a; ++a; }
        const int b = a + t;
        run_tile<4>(smem, sb, a * 128, b * 128, a, b != a, targets);
    } else if (idx < NFULL) {
        const int li = idx - NTILES_TRI;          // [0, 160)
        const int tileM = li >> 4;                // 0..9
        const int tileN = LT + (li & 15);
        run_tile<4>(smem, sb, tileM * 128, tileN * 128, tileM, false, targets);
    } else {
        const int qi = idx - NFULL;               // [0, 384)
        const int t = qi >> 2;                    // [0, 96)
        const int tileM = 10 + (t >> 4);          // 10..15
        const int tileN = LT + (t & 15);
        const int colBase = tileN * 128 + (qi & 3) * 32;
        run_tile<1>(smem, sb, tileM * 128, colBase, tileM, false, targets);
    }
}

// ---------------------------------------------------------------------------
// Kernel 3: deterministic final reduction -> scalar loss. 1024 threads.
// ---------------------------------------------------------------------------
__global__ void loss_kernel(float* __restrict__ out) {
    const int tid = threadIdx.x;
    float s = 0.f;
    for (int r = tid; r < HALF; r += 1024) {
        const float4* ap4 = reinterpret_cast<const float4*>(g_ap + (size_t)r * NSLOT);
        const float4* an4 = reinterpret_cast<const float4*>(g_an + (size_t)r * NSLOT);
        float ap = -1e30f, an = 1e30f;
        #pragma unroll
        for (int t = 0; t < NSLOT / 4; t++) {
            float4 a = ap4[t], b = an4[t];
            ap = fmaxf(ap, fmaxf(fmaxf(a.x, a.y), fmaxf(a.z, a.w)));
            an = fminf(an, fminf(fminf(b.x, b.y), fminf(b.z, b.w)));
        }
        s += fmaxf(ap - an + MARGIN_F, 0.f);
    }
    #pragma unroll
    for (int o = 16; o > 0; o >>= 1) s += __shfl_xor_sync(0xffffffffu, s, o);
    __shared__ float sm[32];
    if ((tid & 31) == 0) sm[tid >> 5] = s;
    __syncthreads();
    if (tid == 0) {
        float t = 0.f;
        #pragma unroll
        for (int i = 0; i < 32; i++) t += sm[i];
        out[0] = t / (float)HALF;
    }
}

// ---------------------------------------------------------------------------
extern "C" void kernel_launch(void* const* d_in, const int* in_sizes, int n_in,
                              void* d_out, int out_size) {
    const float* A       = (const float*)d_in[0];   // [4096, 2048] fp32
    const int*   targets = (const int*)d_in[1];     // [4096] int32
    (void)in_sizes; (void)n_in; (void)out_size;
    float* out = (float*)d_out;

    cudaFuncSetAttribute(dist_imma_kernel,
                         cudaFuncAttributeMaxDynamicSharedMemorySize, SMEM_TOTAL);

    quant_sq_kernel<<<N_ROWS, 128>>>(A);
    dist_imma_kernel<<<NBLOCKS, 256, SMEM_TOTAL>>>(targets);
    loss_kernel<<<1, 1024>>>(out);
}

// round 11
// speedup vs baseline: 1.8406x; 1.8406x over previous
#include <cuda_runtime.h>
#include <cuda_bf16.h>
#include <cstdint>

// ---------------------------------------------------------------------------
// Problem constants
// ---------------------------------------------------------------------------
#define N_ROWS 4096
#define DIM    2048
#define HALF   2048
#define TILE_M 128
#define TILE_N 128
#define KC     128                // int8 elems per K chunk (128 B per row)
#define NKC    (DIM / KC)         // 16 chunks
#define NT_COL (N_ROWS / TILE_N)  // 32 column-tile slots per row
#define LT     16                 // left-half tiles per side (2048/128)
#define NTILES_TRI (LT * (LT + 1) / 2)          // 136 upper-tri incl diag
#define NTILES_TOT (NTILES_TRI + LT * LT)       // 136 + 256 = 392
#define MARGIN_F 0.3f
#define SLAB_BYTES ((size_t)N_ROWS * 128)   // bytes per K-chunk slab in g_Aq

// SMEM layout (dynamic)
#define STAGE_BYTES 32768         // A tile 16KB + B tile 16KB
#define STAGES 3
#define OFF_MBAR 98304            // 3 x 8B mbarriers
#define OFF_SQC  98432
#define OFF_TGC  98944
#define OFF_SQR  99456
#define OFF_TGR  99968
#define OFF_SCR  100480           // row quant scales
#define OFF_SCC  100992           // col quant scales
#define OFF_RAP  101504           // 128*4 floats (row partials)
#define OFF_RAN  103552
#define OFF_CAP  105600           // 128*2 floats (col partials, transposed out)
#define OFF_CAN  106624
#define SMEM_TOTAL 107648

// Scratch (__device__ globals; allocation-free rule)
// g_Aq layout: [chunk][row][128B], SW128 swizzle pre-applied, so a 128-row tile
// slab is 16KB contiguous and bulk-copies directly into the ldmatrix-ready image.
__device__ __align__(128) int8_t g_Aq[(size_t)N_ROWS * DIM];   // 8 MB
__device__ float g_sq[N_ROWS];
__device__ float g_scale[N_ROWS];
__device__ float g_ap[HALF * NT_COL];
__device__ float g_an[HALF * NT_COL];

// ---------------------------------------------------------------------------
// PTX helpers
// ---------------------------------------------------------------------------
__device__ __forceinline__ uint32_t smem_u32(const void* p) {
    uint32_t a;
    asm("{ .reg .u64 t; cvta.to.shared.u64 t, %1; cvt.u32.u64 %0, t; }" : "=r"(a) : "l"(p));
    return a;
}
__device__ __forceinline__ void mbar_init(uint32_t a, uint32_t cnt) {
    asm volatile("mbarrier.init.shared.b64 [%0], %1;" :: "r"(a), "r"(cnt) : "memory");
}
__device__ __forceinline__ void mbar_expect_tx(uint32_t a, uint32_t bytes) {
    asm volatile("mbarrier.arrive.expect_tx.shared.b64 _, [%0], %1;"
                 :: "r"(a), "r"(bytes) : "memory");
}
__device__ __forceinline__ void mbar_wait(uint32_t a, uint32_t parity) {
    asm volatile(
        "{\n\t.reg .pred P;\n"
        "W_%=:\n\t"
        "mbarrier.try_wait.parity.shared.b64 P, [%0], %1, 0x989680;\n\t"
        "@P bra.uni D_%=;\n\t"
        "bra.uni W_%=;\n"
        "D_%=:\n\t}"
        :: "r"(a), "r"(parity) : "memory");
}
__device__ __forceinline__ void bulk_g2s(uint32_t sdst, const void* gsrc,
                                         uint32_t bytes, uint32_t mbar) {
    asm volatile(
        "cp.async.bulk.shared::cta.global.mbarrier::complete_tx::bytes [%0], [%1], %2, [%3];"
        :: "r"(sdst), "l"(gsrc), "r"(bytes), "r"(mbar) : "memory");
}
__device__ __forceinline__ void ldmatrix_x4(uint32_t* r, uint32_t addr) {
    asm volatile("ldmatrix.sync.aligned.m8n8.x4.shared.b16 {%0,%1,%2,%3}, [%4];"
                 : "=r"(r[0]), "=r"(r[1]), "=r"(r[2]), "=r"(r[3]) : "r"(addr));
}
__device__ __forceinline__ void mma_s8(int* c, const uint32_t* a, uint32_t b0, uint32_t b1) {
    asm volatile(
        "mma.sync.aligned.m16n8k32.row.col.s32.s8.s8.s32 "
        "{%0,%1,%2,%3}, {%4,%5,%6,%7}, {%8,%9}, {%0,%1,%2,%3};"
        : "+r"(c[0]), "+r"(c[1]), "+r"(c[2]), "+r"(c[3])
        : "r"(a[0]), "r"(a[1]), "r"(a[2]), "r"(a[3]), "r"(b0), "r"(b1));
}
// SW128 swizzle on a 128-byte row: 16B chunk index XOR (row & 7)
__device__ __forceinline__ uint32_t sw_off(uint32_t r, uint32_t c8) {
    return r * 128u + ((c8 ^ (r & 7u)) << 4);
}

// ---------------------------------------------------------------------------
// Kernel 1: per-row absmax quantize fp32 -> int8 (pre-swizzled chunk-blocked
// layout) + row sum-of-squares (fp32). One block (128 thr, MLP 4) per row.
// ---------------------------------------------------------------------------
__global__ void quant_sq_kernel(const float* __restrict__ A) {
    const int row = blockIdx.x;
    const int tid = threadIdx.x;
    const float4* a4 = reinterpret_cast<const float4*>(A + (size_t)row * DIM);
    float4 v[4];
    #pragma unroll
    for (int i = 0; i < 4; i++) v[i] = a4[tid + i * 128];

    float s = 0.f, m = 0.f;
    #pragma unroll
    for (int i = 0; i < 4; i++) {
        s += v[i].x * v[i].x + v[i].y * v[i].y + v[i].z * v[i].z + v[i].w * v[i].w;
        m = fmaxf(m, fmaxf(fmaxf(fabsf(v[i].x), fabsf(v[i].y)),
                           fmaxf(fabsf(v[i].z), fabsf(v[i].w))));
    }
    #pragma unroll
    for (int o = 16; o > 0; o >>= 1) {
        s += __shfl_xor_sync(0xffffffffu, s, o);
        m = fmaxf(m, __shfl_xor_sync(0xffffffffu, m, o));
    }
    __shared__ float sm_s[4], sm_m[4];
    if ((tid & 31) == 0) { sm_s[tid >> 5] = s; sm_m[tid >> 5] = m; }
    __syncthreads();
    float ts = sm_s[0] + sm_s[1] + sm_s[2] + sm_s[3];
    float tm = fmaxf(fmaxf(sm_m[0], sm_m[1]), fmaxf(sm_m[2], sm_m[3]));
    if (tid == 0) {
        g_sq[row] = ts;
        g_scale[row] = fmaxf(tm, 1e-30f) / 127.0f;
    }
    const float inv = 127.0f / fmaxf(tm, 1e-30f);

    uint32_t* q32 = reinterpret_cast<uint32_t*>(g_Aq);
    auto pack = [inv](float4 vv) -> uint32_t {
        int q0 = __float2int_rn(vv.x * inv), q1 = __float2int_rn(vv.y * inv);
        int q2 = __float2int_rn(vv.z * inv), q3 = __float2int_rn(vv.w * inv);
        return (uint32_t)(uint8_t)(int8_t)q0 | ((uint32_t)(uint8_t)(int8_t)q1 << 8) |
               ((uint32_t)(uint8_t)(int8_t)q2 << 16) | ((uint32_t)(uint8_t)(int8_t)q3 << 24);
    };
    // j32 = 4-byte column index in [0, 512). chunk = j32>>5; c8 = (j32>>2)&7.
    auto qidx = [row](int j32) -> size_t {
        const int c  = j32 >> 5;
        const int c8 = (j32 >> 2) & 7;
        const int ww = j32 & 3;
        const size_t byteoff = (size_t)c * SLAB_BYTES + (size_t)row * 128 +
                               (size_t)(((uint32_t)c8 ^ ((uint32_t)row & 7u)) << 4) + ww * 4;
        return byteoff >> 2;
    };
    #pragma unroll
    for (int i = 0; i < 4; i++) q32[qidx(tid + i * 128)] = pack(v[i]);
}

// ---------------------------------------------------------------------------
// Kernel 2: int8 warp-MMA Gram tile (128x128) + fused dist/mask/max-min.
// Symmetric schedule: 136 upper-tri left-half tiles (off-diagonal ones also
// emit transposed column partials) + 256 right-half tiles. 392 uniform blocks.
// 256 threads = 8 warps in 2x4 (each warp 64x32).
// ---------------------------------------------------------------------------
__global__ __launch_bounds__(256, 2)
void dist_imma_kernel(const int* __restrict__ targets) {
    extern __shared__ __align__(128) char smem[];
    const uint32_t sb = smem_u32(smem);
    const int tid = threadIdx.x;
    const int lane = tid & 31;
    const int w = tid >> 5;

    // ---- tile decode ----
    int tileM, tileN;
    bool doTrans;
    {
        int idx = blockIdx.x;
        if (idx < NTILES_TRI) {
            int a = 0, t = idx;
            #pragma unroll 1
            while (t >= LT - a) { t -= LT - a; ++a; }
            tileM = a; tileN = a + t;
            doTrans = (tileN != tileM);
        } else {
            int li = idx - NTILES_TRI;
            tileM = li >> 4;
            tileN = LT + (li & 15);
            doTrans = false;
        }
    }
    const int rowBase = tileM * TILE_M;
    const int colBase = tileN * TILE_N;

    float* s_sqc = reinterpret_cast<float*>(smem + OFF_SQC);
    int*   s_tgc = reinterpret_cast<int*>(smem + OFF_TGC);
    float* s_sqr = reinterpret_cast<float*>(smem + OFF_SQR);
    int*   s_tgr = reinterpret_cast<int*>(smem + OFF_TGR);
    float* s_scr = reinterpret_cast<float*>(smem + OFF_SCR);
    float* s_scc = reinterpret_cast<float*>(smem + OFF_SCC);
    float* s_rap = reinterpret_cast<float*>(smem + OFF_RAP);
    float* s_ran = reinterpret_cast<float*>(smem + OFF_RAN);
    float* s_cap = reinterpret_cast<float*>(smem + OFF_CAP);
    float* s_can = reinterpret_cast<float*>(smem + OFF_CAN);

    if (tid == 0) {
        #pragma unroll
        for (int s = 0; s < STAGES; ++s) mbar_init(sb + OFF_MBAR + s * 8, 1);
    }
    if (tid < TILE_N) {
        s_sqc[tid] = g_sq[colBase + tid];
        s_tgc[tid] = targets[colBase + tid];
        s_scc[tid] = g_scale[colBase + tid];
        s_sqr[tid] = g_sq[rowBase + tid];
        s_tgr[tid] = targets[rowBase + tid];
        s_scr[tid] = g_scale[rowBase + tid];
    }
    __syncthreads();

    auto issue_chunk = [&](int s, int chunk) {
        const uint32_t mbar = sb + OFF_MBAR + s * 8;
        const uint32_t st = sb + (uint32_t)s * STAGE_BYTES;
        mbar_expect_tx(mbar, STAGE_BYTES);
        bulk_g2s(st, g_Aq + (size_t)chunk * SLAB_BYTES + (size_t)rowBase * 128,
                 16384u, mbar);
        bulk_g2s(st + 16384u, g_Aq + (size_t)chunk * SLAB_BYTES + (size_t)colBase * 128,
                 16384u, mbar);
    };
    if (tid == 0) {
        issue_chunk(0, 0);
        issue_chunk(1, 1);
        issue_chunk(2, 2);
    }

    int acc[4][4][4];
    #pragma unroll
    for (int i = 0; i < 4; i++)
        #pragma unroll
        for (int j = 0; j < 4; j++)
            #pragma unroll
            for (int e = 0; e < 4; e++) acc[i][j][e] = 0;

    const int mBase = (w >> 2) * 64;
    const int nBase = (w & 3) * 32;
    uint32_t ph0 = 0, ph1 = 0, ph2 = 0;

    for (int c = 0; c < NKC; ++c) {
        const int s = c % STAGES;
        uint32_t& ph = (s == 0) ? ph0 : (s == 1) ? ph1 : ph2;
        mbar_wait(sb + OFF_MBAR + s * 8, ph & 1);
        ph++;

        const uint32_t stA = sb + (uint32_t)s * STAGE_BYTES;
        const uint32_t stB = stA + 16384u;
        #pragma unroll
        for (int ks = 0; ks < 4; ++ks) {        // 4 x k32(int8) per 128-chunk
            uint32_t a[4][4];
            #pragma unroll
            for (int mi = 0; mi < 4; ++mi) {
                const uint32_t r = mBase + mi * 16 + (lane & 15);
                const uint32_t c8 = ks * 2 + (lane >> 4);
                ldmatrix_x4(a[mi], stA + sw_off(r, c8));
            }
            uint32_t b[2][4];
            #pragma unroll
            for (int nb = 0; nb < 2; ++nb) {
                const uint32_t r = nBase + nb * 16 + ((lane >> 4) << 3) + (lane & 7);
                const uint32_t c8 = ks * 2 + ((lane >> 3) & 1);
                ldmatrix_x4(b[nb], stB + sw_off(r, c8));
            }
            #pragma unroll
            for (int mi = 0; mi < 4; ++mi)
                #pragma unroll
                for (int nj = 0; nj < 4; ++nj)
                    mma_s8(acc[mi][nj], a[mi], b[nj >> 1][(nj & 1) * 2],
                           b[nj >> 1][(nj & 1) * 2 + 1]);
        }
        __syncthreads();               // all warps done with stage s
        if (tid == 0 && c + STAGES < NKC) issue_chunk(s, c + STAGES);
    }

    // ---- Epilogue ----
    const int qrow = lane >> 2;
    const int qcol = lane & 3;

    // Pass 0: int accumulators -> distances in place (bitcast storage).
    float* dv = reinterpret_cast<float*>(&acc[0][0][0]);
    #pragma unroll
    for (int mi = 0; mi < 4; ++mi) {
        #pragma unroll
        for (int h = 0; h < 2; ++h) {
            const int rl = mBase + mi * 16 + qrow + h * 8;
            const float sqr = s_sqr[rl];
            const float sr2 = 2.0f * s_scr[rl];
            #pragma unroll
            for (int nj = 0; nj < 4; ++nj) {
                #pragma unroll
                for (int cc = 0; cc < 2; ++cc) {
                    const int cl = nBase + nj * 8 + qcol * 2 + cc;
                    const int e = h * 2 + cc;
                    const float dot = sr2 * s_scc[cl] * (float)acc[mi][nj][e];
                    const float d2 = sqr + s_sqc[cl] - dot;
                    dv[(mi * 4 + nj) * 4 + e] = sqrtf(fmaxf(d2, 1e-12f));
                }
            }
        }
    }

    // Pass 1: row-side masked max/min.
    #pragma unroll
    for (int mi = 0; mi < 4; ++mi) {
        #pragma unroll
        for (int h = 0; h < 2; ++h) {
            const int rl = mBase + mi * 16 + qrow + h * 8;
            const int tgr = s_tgr[rl];
            float ap = -1e30f, an = 1e30f;
            #pragma unroll
            for (int nj = 0; nj < 4; ++nj) {
                #pragma unroll
                for (int cc = 0; cc < 2; ++cc) {
                    const int cl = nBase + nj * 8 + qcol * 2 + cc;
                    const float d = dv[(mi * 4 + nj) * 4 + h * 2 + cc];
                    if (s_tgc[cl] == tgr) ap = fmaxf(ap, d);
                    else                  an = fminf(an, d);
                }
            }
            ap = fmaxf(ap, __shfl_xor_sync(0xffffffffu, ap, 1));
            ap = fmaxf(ap, __shfl_xor_sync(0xffffffffu, ap, 2));
            an = fminf(an, __shfl_xor_sync(0xffffffffu, an, 1));
            an = fminf(an, __shfl_xor_sync(0xffffffffu, an, 2));
            if (qcol == 0) {
                s_rap[rl * 4 + (w & 3)] = ap;
                s_ran[rl * 4 + (w & 3)] = an;
            }
        }
    }

    // Pass 2 (off-diagonal tri tiles): column-side masked max/min —
    // the transposed tile's row reduction (mask symmetric, d symmetric).
    if (doTrans) {
        #pragma unroll
        for (int nj = 0; nj < 4; ++nj) {
            #pragma unroll
            for (int cc = 0; cc < 2; ++cc) {
                const int cl = nBase + nj * 8 + qcol * 2 + cc;
                const int tgc = s_tgc[cl];
                float ap = -1e30f, an = 1e30f;
                #pragma unroll
                for (int mi = 0; mi < 4; ++mi) {
                    #pragma unroll
                    for (int h = 0; h < 2; ++h) {
                        const int rl = mBase + mi * 16 + qrow + h * 8;
                        const float d = dv[(mi * 4 + nj) * 4 + h * 2 + cc];
                        if (s_tgr[rl] == tgc) ap = fmaxf(ap, d);
                        else                  an = fminf(an, d);
                    }
                }
                ap = fmaxf(ap, __shfl_xor_sync(0xffffffffu, ap, 4));
                ap = fmaxf(ap, __shfl_xor_sync(0xffffffffu, ap, 8));
                ap = fmaxf(ap, __shfl_xor_sync(0xffffffffu, ap, 16));
                an = fminf(an, __shfl_xor_sync(0xffffffffu, an, 4));
                an = fminf(an, __shfl_xor_sync(0xffffffffu, an, 8));
                an = fminf(an, __shfl_xor_sync(0xffffffffu, an, 16));
                if (qrow == 0) {
                    s_cap[cl * 2 + (w >> 2)] = ap;
                    s_can[cl * 2 + (w >> 2)] = an;
                }
            }
        }
    }
    __syncthreads();

    if (tid < TILE_M) {
        float ap = -1e30f, an = 1e30f;
        #pragma unroll
        for (int t = 0; t < 4; ++t) {
            ap = fmaxf(ap, s_rap[tid * 4 + t]);
            an = fminf(an, s_ran[tid * 4 + t]);
        }
        g_ap[(size_t)(rowBase + tid) * NT_COL + tileN] = ap;
        g_an[(size_t)(rowBase + tid) * NT_COL + tileN] = an;
        if (doTrans) {
            const float cap = fmaxf(s_cap[tid * 2], s_cap[tid * 2 + 1]);
            const float can = fminf(s_can[tid * 2], s_can[tid * 2 + 1]);
            g_ap[(size_t)(colBase + tid) * NT_COL + tileM] = cap;
            g_an[(size_t)(colBase + tid) * NT_COL + tileM] = can;
        }
    }
}

// ---------------------------------------------------------------------------
// Kernel 3: deterministic final reduction -> scalar loss. 1024 threads.
// ---------------------------------------------------------------------------
__global__ void loss_kernel(float* __restrict__ out) {
    const int tid = threadIdx.x;
    float s = 0.f;
    for (int r = tid; r < HALF; r += 1024) {
        const float4* ap4 = reinterpret_cast<const float4*>(g_ap + (size_t)r * NT_COL);
        const float4* an4 = reinterpret_cast<const float4*>(g_an + (size_t)r * NT_COL);
        float ap = -1e30f, an = 1e30f;
        #pragma unroll
        for (int t = 0; t < NT_COL / 4; t++) {
            float4 a = ap4[t], b = an4[t];
            ap = fmaxf(ap, fmaxf(fmaxf(a.x, a.y), fmaxf(a.z, a.w)));
            an = fminf(an, fminf(fminf(b.x, b.y), fminf(b.z, b.w)));
        }
        s += fmaxf(ap - an + MARGIN_F, 0.f);
    }
    #pragma unroll
    for (int o = 16; o > 0; o >>= 1) s += __shfl_xor_sync(0xffffffffu, s, o);
    __shared__ float sm[32];
    if ((tid & 31) == 0) sm[tid >> 5] = s;
    __syncthreads();
    if (tid == 0) {
        float t = 0.f;
        #pragma unroll
        for (int i = 0; i < 32; i++) t += sm[i];
        out[0] = t / (float)HALF;
    }
}

// ---------------------------------------------------------------------------
extern "C" void kernel_launch(void* const* d_in, const int* in_sizes, int n_in,
                              void* d_out, int out_size) {
    const float* A       = (const float*)d_in[0];   // [4096, 2048] fp32
    const int*   targets = (const int*)d_in[1];     // [4096] int32
    (void)in_sizes; (void)n_in; (void)out_size;
    float* out = (float*)d_out;

    cudaFuncSetAttribute(dist_imma_kernel,
                         cudaFuncAttributeMaxDynamicSharedMemorySize, SMEM_TOTAL);

    quant_sq_kernel<<<N_ROWS, 128>>>(A);
    dist_imma_kernel<<<NTILES_TOT, 256, SMEM_TOTAL>>>(targets);
    loss_kernel<<<1, 1024>>>(out);
}

// round 12
// speedup vs baseline: 1.9539x; 1.0616x over previous
#include <cuda_runtime.h>
#include <cuda_bf16.h>
#include <cstdint>

// ---------------------------------------------------------------------------
// Problem constants
// ---------------------------------------------------------------------------
#define N_ROWS 4096
#define DIM    2048
#define HALF   2048
#define TILE_M 128
#define TILE_N 128
#define KC     128                // int8 elems per K chunk (128 B per row)
#define NKC    (DIM / KC)         // 16 chunks
#define NT_COL (N_ROWS / TILE_N)  // 32 column-tile slots per row
#define LT     16                 // left-half tiles per side (2048/128)
#define NTILES_TRI (LT * (LT + 1) / 2)          // 136 upper-tri incl diag
#define NTILES_TOT (NTILES_TRI + LT * LT)       // 136 + 256 = 392
#define MARGIN_F 0.3f
#define SLAB_BYTES ((size_t)N_ROWS * 128)   // bytes per K-chunk slab in g_Aq

// SMEM layout (dynamic)
#define STAGE_BYTES 32768         // A tile 16KB + B tile 16KB
#define STAGES 3
#define OFF_MBAR 98304            // 3 x 8B mbarriers
#define OFF_SQC  98432
#define OFF_TGC  98944
#define OFF_SQR  99456
#define OFF_TGR  99968
#define OFF_SCR  100480           // row quant scales
#define OFF_SCC  100992           // col quant scales
#define OFF_RAP  101504           // 128*4 floats (row partials, d^2 space)
#define OFF_RAN  103552
#define OFF_CAP  105600           // 128*2 floats (col partials, d^2 space)
#define OFF_CAN  106624
#define SMEM_TOTAL 107648

// Scratch (__device__ globals; allocation-free rule)
// g_Aq layout: [chunk][row][128B], SW128 swizzle pre-applied, so a 128-row tile
// slab is 16KB contiguous and bulk-copies directly into the ldmatrix-ready image.
__device__ __align__(128) int8_t g_Aq[(size_t)N_ROWS * DIM];   // 8 MB
__device__ float g_sq[N_ROWS];
__device__ float g_scale[N_ROWS];
__device__ float g_ap[HALF * NT_COL];   // d^2-space partial maxima
__device__ float g_an[HALF * NT_COL];   // d^2-space partial minima

// ---------------------------------------------------------------------------
// PTX helpers
// ---------------------------------------------------------------------------
__device__ __forceinline__ uint32_t smem_u32(const void* p) {
    uint32_t a;
    asm("{ .reg .u64 t; cvta.to.shared.u64 t, %1; cvt.u32.u64 %0, t; }" : "=r"(a) : "l"(p));
    return a;
}
__device__ __forceinline__ void mbar_init(uint32_t a, uint32_t cnt) {
    asm volatile("mbarrier.init.shared.b64 [%0], %1;" :: "r"(a), "r"(cnt) : "memory");
}
__device__ __forceinline__ void mbar_expect_tx(uint32_t a, uint32_t bytes) {
    asm volatile("mbarrier.arrive.expect_tx.shared.b64 _, [%0], %1;"
                 :: "r"(a), "r"(bytes) : "memory");
}
__device__ __forceinline__ void mbar_wait(uint32_t a, uint32_t parity) {
    asm volatile(
        "{\n\t.reg .pred P;\n"
        "W_%=:\n\t"
        "mbarrier.try_wait.parity.shared.b64 P, [%0], %1, 0x989680;\n\t"
        "@P bra.uni D_%=;\n\t"
        "bra.uni W_%=;\n"
        "D_%=:\n\t}"
        :: "r"(a), "r"(parity) : "memory");
}
__device__ __forceinline__ void bulk_g2s(uint32_t sdst, const void* gsrc,
                                         uint32_t bytes, uint32_t mbar) {
    asm volatile(
        "cp.async.bulk.shared::cta.global.mbarrier::complete_tx::bytes [%0], [%1], %2, [%3];"
        :: "r"(sdst), "l"(gsrc), "r"(bytes), "r"(mbar) : "memory");
}
__device__ __forceinline__ void ldmatrix_x4(uint32_t* r, uint32_t addr) {
    asm volatile("ldmatrix.sync.aligned.m8n8.x4.shared.b16 {%0,%1,%2,%3}, [%4];"
                 : "=r"(r[0]), "=r"(r[1]), "=r"(r[2]), "=r"(r[3]) : "r"(addr));
}
__device__ __forceinline__ void mma_s8(int* c, const uint32_t* a, uint32_t b0, uint32_t b1) {
    asm volatile(
        "mma.sync.aligned.m16n8k32.row.col.s32.s8.s8.s32 "
        "{%0,%1,%2,%3}, {%4,%5,%6,%7}, {%8,%9}, {%0,%1,%2,%3};"
        : "+r"(c[0]), "+r"(c[1]), "+r"(c[2]), "+r"(c[3])
        : "r"(a[0]), "r"(a[1]), "r"(a[2]), "r"(a[3]), "r"(b0), "r"(b1));
}
// SW128 swizzle on a 128-byte row: 16B chunk index XOR (row & 7)
__device__ __forceinline__ uint32_t sw_off(uint32_t r, uint32_t c8) {
    return r * 128u + ((c8 ^ (r & 7u)) << 4);
}

// ---------------------------------------------------------------------------
// Kernel 1: per-row absmax quantize fp32 -> int8 (pre-swizzled chunk-blocked
// layout) + row sum-of-squares (fp32). One block (128 thr, MLP 4) per row.
// ---------------------------------------------------------------------------
__global__ void quant_sq_kernel(const float* __restrict__ A) {
    const int row = blockIdx.x;
    const int tid = threadIdx.x;
    const float4* a4 = reinterpret_cast<const float4*>(A + (size_t)row * DIM);
    float4 v[4];
    #pragma unroll
    for (int i = 0; i < 4; i++) v[i] = a4[tid + i * 128];

    float s = 0.f, m = 0.f;
    #pragma unroll
    for (int i = 0; i < 4; i++) {
        s += v[i].x * v[i].x + v[i].y * v[i].y + v[i].z * v[i].z + v[i].w * v[i].w;
        m = fmaxf(m, fmaxf(fmaxf(fabsf(v[i].x), fabsf(v[i].y)),
                           fmaxf(fabsf(v[i].z), fabsf(v[i].w))));
    }
    #pragma unroll
    for (int o = 16; o > 0; o >>= 1) {
        s += __shfl_xor_sync(0xffffffffu, s, o);
        m = fmaxf(m, __shfl_xor_sync(0xffffffffu, m, o));
    }
    __shared__ float sm_s[4], sm_m[4];
    if ((tid & 31) == 0) { sm_s[tid >> 5] = s; sm_m[tid >> 5] = m; }
    __syncthreads();
    float ts = sm_s[0] + sm_s[1] + sm_s[2] + sm_s[3];
    float tm = fmaxf(fmaxf(sm_m[0], sm_m[1]), fmaxf(sm_m[2], sm_m[3]));
    if (tid == 0) {
        g_sq[row] = ts;
        g_scale[row] = fmaxf(tm, 1e-30f) / 127.0f;
    }
    const float inv = 127.0f / fmaxf(tm, 1e-30f);

    uint32_t* q32 = reinterpret_cast<uint32_t*>(g_Aq);
    auto pack = [inv](float4 vv) -> uint32_t {
        int q0 = __float2int_rn(vv.x * inv), q1 = __float2int_rn(vv.y * inv);
        int q2 = __float2int_rn(vv.z * inv), q3 = __float2int_rn(vv.w * inv);
        return (uint32_t)(uint8_t)(int8_t)q0 | ((uint32_t)(uint8_t)(int8_t)q1 << 8) |
               ((uint32_t)(uint8_t)(int8_t)q2 << 16) | ((uint32_t)(uint8_t)(int8_t)q3 << 24);
    };
    // j32 = 4-byte column index in [0, 512). chunk = j32>>5; c8 = (j32>>2)&7.
    auto qidx = [row](int j32) -> size_t {
        const int c  = j32 >> 5;
        const int c8 = (j32 >> 2) & 7;
        const int ww = j32 & 3;
        const size_t byteoff = (size_t)c * SLAB_BYTES + (size_t)row * 128 +
                               (size_t)(((uint32_t)c8 ^ ((uint32_t)row & 7u)) << 4) + ww * 4;
        return byteoff >> 2;
    };
    #pragma unroll
    for (int i = 0; i < 4; i++) q32[qidx(tid + i * 128)] = pack(v[i]);
}

// ---------------------------------------------------------------------------
// Kernel 2: int8 warp-MMA Gram tile (128x128) + fused d^2/mask/max-min.
// d^2-space reduction: sqrt is monotone, so max/min selection over d^2 picks
// the same elements; sqrt is applied once per row in loss_kernel (bit-exact).
// Symmetric schedule: 136 upper-tri left-half tiles (off-diagonal ones also
// emit transposed column partials) + 256 right-half tiles. 392 uniform blocks.
// 256 threads = 8 warps in 2x4 (each warp 64x32).
// ---------------------------------------------------------------------------
__global__ __launch_bounds__(256, 2)
void dist_imma_kernel(const int* __restrict__ targets) {
    extern __shared__ __align__(128) char smem[];
    const uint32_t sb = smem_u32(smem);
    const int tid = threadIdx.x;
    const int lane = tid & 31;
    const int w = tid >> 5;

    // ---- tile decode ----
    int tileM, tileN;
    bool doTrans;
    {
        int idx = blockIdx.x;
        if (idx < NTILES_TRI) {
            int a = 0, t = idx;
            #pragma unroll 1
            while (t >= LT - a) { t -= LT - a; ++a; }
            tileM = a; tileN = a + t;
            doTrans = (tileN != tileM);
        } else {
            int li = idx - NTILES_TRI;
            tileM = li >> 4;
            tileN = LT + (li & 15);
            doTrans = false;
        }
    }
    const int rowBase = tileM * TILE_M;
    const int colBase = tileN * TILE_N;

    float* s_sqc = reinterpret_cast<float*>(smem + OFF_SQC);
    int*   s_tgc = reinterpret_cast<int*>(smem + OFF_TGC);
    float* s_sqr = reinterpret_cast<float*>(smem + OFF_SQR);
    int*   s_tgr = reinterpret_cast<int*>(smem + OFF_TGR);
    float* s_scr = reinterpret_cast<float*>(smem + OFF_SCR);
    float* s_scc = reinterpret_cast<float*>(smem + OFF_SCC);
    float* s_rap = reinterpret_cast<float*>(smem + OFF_RAP);
    float* s_ran = reinterpret_cast<float*>(smem + OFF_RAN);
    float* s_cap = reinterpret_cast<float*>(smem + OFF_CAP);
    float* s_can = reinterpret_cast<float*>(smem + OFF_CAN);

    if (tid == 0) {
        #pragma unroll
        for (int s = 0; s < STAGES; ++s) mbar_init(sb + OFF_MBAR + s * 8, 1);
    }
    if (tid < TILE_N) {
        s_sqc[tid] = g_sq[colBase + tid];
        s_tgc[tid] = targets[colBase + tid];
        s_scc[tid] = g_scale[colBase + tid];
        s_sqr[tid] = g_sq[rowBase + tid];
        s_tgr[tid] = targets[rowBase + tid];
        s_scr[tid] = g_scale[rowBase + tid];
    }
    __syncthreads();

    auto issue_chunk = [&](int s, int chunk) {
        const uint32_t mbar = sb + OFF_MBAR + s * 8;
        const uint32_t st = sb + (uint32_t)s * STAGE_BYTES;
        mbar_expect_tx(mbar, STAGE_BYTES);
        bulk_g2s(st, g_Aq + (size_t)chunk * SLAB_BYTES + (size_t)rowBase * 128,
                 16384u, mbar);
        bulk_g2s(st + 16384u, g_Aq + (size_t)chunk * SLAB_BYTES + (size_t)colBase * 128,
                 16384u, mbar);
    };
    if (tid == 0) {
        issue_chunk(0, 0);
        issue_chunk(1, 1);
        issue_chunk(2, 2);
    }

    int acc[4][4][4];
    #pragma unroll
    for (int i = 0; i < 4; i++)
        #pragma unroll
        for (int j = 0; j < 4; j++)
            #pragma unroll
            for (int e = 0; e < 4; e++) acc[i][j][e] = 0;

    const int mBase = (w >> 2) * 64;
    const int nBase = (w & 3) * 32;
    uint32_t ph0 = 0, ph1 = 0, ph2 = 0;

    for (int c = 0; c < NKC; ++c) {
        const int s = c % STAGES;
        uint32_t& ph = (s == 0) ? ph0 : (s == 1) ? ph1 : ph2;
        mbar_wait(sb + OFF_MBAR + s * 8, ph & 1);
        ph++;

        const uint32_t stA = sb + (uint32_t)s * STAGE_BYTES;
        const uint32_t stB = stA + 16384u;
        #pragma unroll
        for (int ks = 0; ks < 4; ++ks) {        // 4 x k32(int8) per 128-chunk
            uint32_t a[4][4];
            #pragma unroll
            for (int mi = 0; mi < 4; ++mi) {
                const uint32_t r = mBase + mi * 16 + (lane & 15);
                const uint32_t c8 = ks * 2 + (lane >> 4);
                ldmatrix_x4(a[mi], stA + sw_off(r, c8));
            }
            uint32_t b[2][4];
            #pragma unroll
            for (int nb = 0; nb < 2; ++nb) {
                const uint32_t r = nBase + nb * 16 + ((lane >> 4) << 3) + (lane & 7);
                const uint32_t c8 = ks * 2 + ((lane >> 3) & 1);
                ldmatrix_x4(b[nb], stB + sw_off(r, c8));
            }
            #pragma unroll
            for (int mi = 0; mi < 4; ++mi)
                #pragma unroll
                for (int nj = 0; nj < 4; ++nj)
                    mma_s8(acc[mi][nj], a[mi], b[nj >> 1][(nj & 1) * 2],
                           b[nj >> 1][(nj & 1) * 2 + 1]);
        }
        __syncthreads();               // all warps done with stage s
        if (tid == 0 && c + STAGES < NKC) issue_chunk(s, c + STAGES);
    }

    // ---- Epilogue (d^2 space, no sqrt) ----
    const int qrow = lane >> 2;
    const int qcol = lane & 3;

    // Pass 0: int accumulators -> clamped d^2 in place (bitcast storage).
    float* dv = reinterpret_cast<float*>(&acc[0][0][0]);
    #pragma unroll
    for (int mi = 0; mi < 4; ++mi) {
        #pragma unroll
        for (int h = 0; h < 2; ++h) {
            const int rl = mBase + mi * 16 + qrow + h * 8;
            const float sqr = s_sqr[rl];
            const float sr2 = 2.0f * s_scr[rl];
            #pragma unroll
            for (int nj = 0; nj < 4; ++nj) {
                #pragma unroll
                for (int cc = 0; cc < 2; ++cc) {
                    const int cl = nBase + nj * 8 + qcol * 2 + cc;
                    const int e = h * 2 + cc;
                    const float dot = sr2 * s_scc[cl] * (float)acc[mi][nj][e];
                    const float d2 = sqr + s_sqc[cl] - dot;
                    dv[(mi * 4 + nj) * 4 + e] = fmaxf(d2, 1e-12f);
                }
            }
        }
    }

    // Pass 1: row-side masked max/min over d^2.
    #pragma unroll
    for (int mi = 0; mi < 4; ++mi) {
        #pragma unroll
        for (int h = 0; h < 2; ++h) {
            const int rl = mBase + mi * 16 + qrow + h * 8;
            const int tgr = s_tgr[rl];
            float ap = -1e30f, an = 1e30f;
            #pragma unroll
            for (int nj = 0; nj < 4; ++nj) {
                #pragma unroll
                for (int cc = 0; cc < 2; ++cc) {
                    const int cl = nBase + nj * 8 + qcol * 2 + cc;
                    const float d = dv[(mi * 4 + nj) * 4 + h * 2 + cc];
                    if (s_tgc[cl] == tgr) ap = fmaxf(ap, d);
                    else                  an = fminf(an, d);
                }
            }
            ap = fmaxf(ap, __shfl_xor_sync(0xffffffffu, ap, 1));
            ap = fmaxf(ap, __shfl_xor_sync(0xffffffffu, ap, 2));
            an = fminf(an, __shfl_xor_sync(0xffffffffu, an, 1));
            an = fminf(an, __shfl_xor_sync(0xffffffffu, an, 2));
            if (qcol == 0) {
                s_rap[rl * 4 + (w & 3)] = ap;
                s_ran[rl * 4 + (w & 3)] = an;
            }
        }
    }

    // Pass 2 (off-diagonal tri tiles): column-side masked max/min over d^2 —
    // the transposed tile's row reduction (mask symmetric, d^2 symmetric).
    if (doTrans) {
        #pragma unroll
        for (int nj = 0; nj < 4; ++nj) {
            #pragma unroll
            for (int cc = 0; cc < 2; ++cc) {
                const int cl = nBase + nj * 8 + qcol * 2 + cc;
                const int tgc = s_tgc[cl];
                float ap = -1e30f, an = 1e30f;
                #pragma unroll
                for (int mi = 0; mi < 4; ++mi) {
                    #pragma unroll
                    for (int h = 0; h < 2; ++h) {
                        const int rl = mBase + mi * 16 + qrow + h * 8;
                        const float d = dv[(mi * 4 + nj) * 4 + h * 2 + cc];
                        if (s_tgr[rl] == tgc) ap = fmaxf(ap, d);
                        else                  an = fminf(an, d);
                    }
                }
                ap = fmaxf(ap, __shfl_xor_sync(0xffffffffu, ap, 4));
                ap = fmaxf(ap, __shfl_xor_sync(0xffffffffu, ap, 8));
                ap = fmaxf(ap, __shfl_xor_sync(0xffffffffu, ap, 16));
                an = fminf(an, __shfl_xor_sync(0xffffffffu, an, 4));
                an = fminf(an, __shfl_xor_sync(0xffffffffu, an, 8));
                an = fminf(an, __shfl_xor_sync(0xffffffffu, an, 16));
                if (qrow == 0) {
                    s_cap[cl * 2 + (w >> 2)] = ap;
                    s_can[cl * 2 + (w >> 2)] = an;
                }
            }
        }
    }
    __syncthreads();

    if (tid < TILE_M) {
        float ap = -1e30f, an = 1e30f;
        #pragma unroll
        for (int t = 0; t < 4; ++t) {
            ap = fmaxf(ap, s_rap[tid * 4 + t]);
            an = fminf(an, s_ran[tid * 4 + t]);
        }
        g_ap[(size_t)(rowBase + tid) * NT_COL + tileN] = ap;
        g_an[(size_t)(rowBase + tid) * NT_COL + tileN] = an;
        if (doTrans) {
            const float cap = fmaxf(s_cap[tid * 2], s_cap[tid * 2 + 1]);
            const float can = fminf(s_can[tid * 2], s_can[tid * 2 + 1]);
            g_ap[(size_t)(colBase + tid) * NT_COL + tileM] = cap;
            g_an[(size_t)(colBase + tid) * NT_COL + tileM] = can;
        }
    }
}

// ---------------------------------------------------------------------------
// Kernel 3: deterministic final reduction -> scalar loss. 1024 threads.
// Applies the deferred sqrt: 2 sqrts per row (bit-identical to per-element).
// ---------------------------------------------------------------------------
__global__ void loss_kernel(float* __restrict__ out) {
    const int tid = threadIdx.x;
    float s = 0.f;
    for (int r = tid; r < HALF; r += 1024) {
        const float4* ap4 = reinterpret_cast<const float4*>(g_ap + (size_t)r * NT_COL);
        const float4* an4 = reinterpret_cast<const float4*>(g_an + (size_t)r * NT_COL);
        float ap = -1e30f, an = 1e30f;
        #pragma unroll
        for (int t = 0; t < NT_COL / 4; t++) {
            float4 a = ap4[t], b = an4[t];
            ap = fmaxf(ap, fmaxf(fmaxf(a.x, a.y), fmaxf(a.z, a.w)));
            an = fminf(an, fminf(fminf(b.x, b.y), fminf(b.z, b.w)));
        }
        s += fmaxf(sqrtf(ap) - sqrtf(an) + MARGIN_F, 0.f);
    }
    #pragma unroll
    for (int o = 16; o > 0; o >>= 1) s += __shfl_xor_sync(0xffffffffu, s, o);
    __shared__ float sm[32];
    if ((tid & 31) == 0) sm[tid >> 5] = s;
    __syncthreads();
    if (tid == 0) {
        float t = 0.f;
        #pragma unroll
        for (int i = 0; i < 32; i++) t += sm[i];
        out[0] = t / (float)HALF;
    }
}

// ---------------------------------------------------------------------------
extern "C" void kernel_launch(void* const* d_in, const int* in_sizes, int n_in,
                              void* d_out, int out_size) {
    const float* A       = (const float*)d_in[0];   // [4096, 2048] fp32
    const int*   targets = (const int*)d_in[1];     // [4096] int32
    (void)in_sizes; (void)n_in; (void)out_size;
    float* out = (float*)d_out;

    cudaFuncSetAttribute(dist_imma_kernel,
                         cudaFuncAttributeMaxDynamicSharedMemorySize, SMEM_TOTAL);

    quant_sq_kernel<<<N_ROWS, 128>>>(A);
    dist_imma_kernel<<<NTILES_TOT, 256, SMEM_TOTAL>>>(targets);
    loss_kernel<<<1, 1024>>>(out);
}